// round 11
// baseline (speedup 1.0000x reference)
#include <cuda_runtime.h>

#define BB 8
#define TT 2048
#define EE 1024
#define HH 128
#define MM (BB*TT)
#define SCALE 0.08838834764831845f   // 1/sqrt(128)

// Scratch for projected Q/K/V (tf32-rounded; Q pre-scaled)
__device__ float g_Q[MM*HH];
__device__ float g_K[MM*HH];
__device__ float g_V[MM*HH];

__device__ __forceinline__ float f2tf(float f) {
    unsigned r;
    asm("cvt.rna.tf32.f32 %0, %1;" : "=r"(r) : "f"(f));
    return __uint_as_float(r);
}

__device__ __forceinline__ void mma_tf32(float* c,
    unsigned a0, unsigned a1, unsigned a2, unsigned a3,
    unsigned b0, unsigned b1)
{
    asm volatile(
        "mma.sync.aligned.m16n8k8.row.col.f32.tf32.tf32.f32 "
        "{%0,%1,%2,%3},{%4,%5,%6,%7},{%8,%9},{%0,%1,%2,%3};"
        : "+f"(c[0]), "+f"(c[1]), "+f"(c[2]), "+f"(c[3])
        : "r"(a0), "r"(a1), "r"(a2), "r"(a3), "r"(b0), "r"(b1));
}
#define U(x) __float_as_uint(x)

// qt permutation: co-resident pairs (x, (x+20)%32) sum to ~31 half-tiles.
__constant__ int QT_MAP[32] = {
    31,27,23,19, 2, 6,10,14,30,26,22,18, 3, 7,11,15,
    29,25,21,17, 0, 4, 8,12,28,24,20,16, 1, 5, 9,13};

// ---------------------------------------------------------------------------
// Kernel 1: QKV projection (tf32 mma). Outputs tf32-rounded; Q pre-scaled.
// ---------------------------------------------------------------------------
__global__ __launch_bounds__(256) void qkv_kernel(
    const float* __restrict__ x,
    const float* __restrict__ Wq,
    const float* __restrict__ Wk,
    const float* __restrict__ Wv)
{
    __shared__ float As[128][36];
    __shared__ float Bs[32][136];

    const int mb = blockIdx.x;
    const int w3 = blockIdx.y;
    const float* Wp   = (w3 == 0) ? Wq : ((w3 == 1) ? Wk : Wv);
    float*       outp = (w3 == 0) ? g_Q : ((w3 == 1) ? g_K : g_V);
    const float  oscale = (w3 == 0) ? SCALE : 1.0f;

    const int tid  = threadIdx.x;
    const int lane = tid & 31;
    const int w    = tid >> 5;
    const int g    = lane >> 2;
    const int t4   = lane & 3;
    const int wm   = (w >> 1) * 32;
    const int wn   = (w & 1) * 64;
    const int m0   = mb * 128;

    float acc[2][8][4];
#pragma unroll
    for (int mt = 0; mt < 2; mt++)
#pragma unroll
        for (int nt = 0; nt < 8; nt++)
#pragma unroll
            for (int i = 0; i < 4; i++) acc[mt][nt][i] = 0.f;

    float4 xa[4], wa[4];
#pragma unroll
    for (int i = 0; i < 4; i++) {
        int lin = tid + i * 256;
        int r = lin >> 3, c = (lin & 7) * 4;
        xa[i] = *(const float4*)&x[(size_t)(m0 + r) * EE + c];
    }
#pragma unroll
    for (int i = 0; i < 4; i++) {
        int lin = tid + i * 256;
        int r = lin >> 5, c = (lin & 31) * 4;
        wa[i] = *(const float4*)&Wp[(size_t)r * HH + c];
    }

    for (int k0 = 0; k0 < EE; k0 += 32) {
#pragma unroll
        for (int i = 0; i < 4; i++) {
            int lin = tid + i * 256;
            int r = lin >> 3, c = (lin & 7) * 4;
            As[r][c + 0] = f2tf(xa[i].x);
            As[r][c + 1] = f2tf(xa[i].y);
            As[r][c + 2] = f2tf(xa[i].z);
            As[r][c + 3] = f2tf(xa[i].w);
        }
#pragma unroll
        for (int i = 0; i < 4; i++) {
            int lin = tid + i * 256;
            int r = lin >> 5, c = (lin & 31) * 4;
            Bs[r][c + 0] = f2tf(wa[i].x);
            Bs[r][c + 1] = f2tf(wa[i].y);
            Bs[r][c + 2] = f2tf(wa[i].z);
            Bs[r][c + 3] = f2tf(wa[i].w);
        }
        __syncthreads();

        if (k0 + 32 < EE) {
            int kn = k0 + 32;
#pragma unroll
            for (int i = 0; i < 4; i++) {
                int lin = tid + i * 256;
                int r = lin >> 3, c = (lin & 7) * 4;
                xa[i] = *(const float4*)&x[(size_t)(m0 + r) * EE + kn + c];
            }
#pragma unroll
            for (int i = 0; i < 4; i++) {
                int lin = tid + i * 256;
                int r = lin >> 5, c = (lin & 31) * 4;
                wa[i] = *(const float4*)&Wp[(size_t)(kn + r) * HH + c];
            }
        }

#pragma unroll
        for (int ks = 0; ks < 4; ks++) {
            unsigned a[2][4];
#pragma unroll
            for (int mt = 0; mt < 2; mt++) {
                a[mt][0] = U(As[wm + mt * 16 + g    ][ks * 8 + t4    ]);
                a[mt][1] = U(As[wm + mt * 16 + g + 8][ks * 8 + t4    ]);
                a[mt][2] = U(As[wm + mt * 16 + g    ][ks * 8 + t4 + 4]);
                a[mt][3] = U(As[wm + mt * 16 + g + 8][ks * 8 + t4 + 4]);
            }
#pragma unroll
            for (int nt = 0; nt < 8; nt++) {
                unsigned b0 = U(Bs[ks * 8 + t4    ][wn + nt * 8 + g]);
                unsigned b1 = U(Bs[ks * 8 + t4 + 4][wn + nt * 8 + g]);
                mma_tf32(acc[0][nt], a[0][0], a[0][1], a[0][2], a[0][3], b0, b1);
                mma_tf32(acc[1][nt], a[1][0], a[1][1], a[1][2], a[1][3], b0, b1);
            }
        }
        __syncthreads();
    }

#pragma unroll
    for (int mt = 0; mt < 2; mt++) {
#pragma unroll
        for (int nt = 0; nt < 8; nt++) {
            int row = m0 + wm + mt * 16 + g;
            int col = wn + nt * 8 + 2 * t4;
            float2 v0 = make_float2(f2tf(acc[mt][nt][0] * oscale), f2tf(acc[mt][nt][1] * oscale));
            float2 v1 = make_float2(f2tf(acc[mt][nt][2] * oscale), f2tf(acc[mt][nt][3] * oscale));
            *(float2*)&outp[(size_t)row * HH + col]       = v0;
            *(float2*)&outp[(size_t)(row + 8) * HH + col] = v1;
        }
    }
}

// ---------------------------------------------------------------------------
// Kernel 2: causal flash attention. 256 threads = 8 warps, 2 CTAs/SM.
// Warp w: rg=w>>1 (16 q-rows), ch=w&1 (k/col half).
//   S: warp computes 16x32 (4 n-tiles); softmax stats exchanged via smem;
//   P written into dead K region as A-frags; O: warp owns 16x64 (8 n-tiles).
// Frag tile = 32 lanes x 4 floats = 512B, no padding (LDS.128 conflict-free).
// ---------------------------------------------------------------------------
#define TILE_F 128
#define ATTN_SMEM ((3*64*TILE_F + 256) * 4)   // 99328 B -> 2 CTAs/SM

__global__ __launch_bounds__(256, 2) void attn_kernel(float* __restrict__ out)
{
    extern __shared__ float sh[];
    float* Qsf  = sh;                  // 64 tiles: [rg 0..3][kc 0..15]
    float* Ksf  = Qsf + 64 * TILE_F;   // 64 tiles: [nt 0..7][ksp 0..7]; P overlays tiles 0..31
    float* Vsf  = Ksf + 64 * TILE_F;   // 64 tiles: [hnt 0..15][ksp 0..3]
    float* smax = Vsf + 64 * TILE_F;   // [2][64] partial row max
    float* ssum = smax + 128;          // [2][64] partial row sum

    const int b  = blockIdx.y;
    const int qt = QT_MAP[blockIdx.x];
    const int q0 = qt * 64;

    const int tid  = threadIdx.x;
    const int lane = tid & 31;
    const int w    = tid >> 5;
    const int g    = lane >> 2;
    const int t4   = lane & 3;
    const int rg   = w >> 1;
    const int ch   = w & 1;
    const int r1   = rg * 16 + g;      // local q-row of lane (first)
    const int r2   = r1 + 8;

    // ---- load Q tile (already tf32+scaled) into A-fragment layout ----
    const float* Qg = g_Q + ((size_t)b * TT + q0) * HH;
#pragma unroll
    for (int it = 0; it < 8; it++) {
        int idx = tid + it * 256;            // 2048 float4
        int r = idx >> 5, c4 = (idx & 31) * 4;
        float4 v = *(const float4*)&Qg[(size_t)r * HH + c4];
        float vv[4] = {v.x, v.y, v.z, v.w};
#pragma unroll
        for (int t = 0; t < 4; t++) {
            int c = c4 + t;
            int ln  = ((r & 7) << 2) | (c & 3);
            int re  = ((r >> 3) & 1) | (((c >> 2) & 1) << 1);
            Qsf[((r >> 4) * 16 + (c >> 3)) * TILE_F + ln * 4 + re] = vv[t];
        }
    }

    float m1 = -1e30f, m2 = -1e30f, l1 = 0.f, l2 = 0.f;
    float o[8][4];
#pragma unroll
    for (int nt = 0; nt < 8; nt++)
#pragma unroll
        for (int i = 0; i < 4; i++) o[nt][i] = 0.f;

    for (int kt = 0; kt <= qt; kt++) {
        if (kt) __syncthreads();    // protect prev iter's P/V reads
        const int k0 = kt * 64;
        const float* Kg = g_K + ((size_t)b * TT + k0) * HH;
        const float* Vg = g_V + ((size_t)b * TT + k0) * HH;

        // ---- load K,V tiles into B-fragment layout ----
#pragma unroll
        for (int it = 0; it < 8; it++) {
            int idx = tid + it * 256;
            int r = idx >> 5, c4 = (idx & 31) * 4;
            float4 kv = *(const float4*)&Kg[(size_t)r * HH + c4];
            float4 vv = *(const float4*)&Vg[(size_t)r * HH + c4];
            {   // K row r = score col n; col c = k
                float va[4] = {kv.x, kv.y, kv.z, kv.w};
#pragma unroll
                for (int t = 0; t < 4; t++) {
                    int c = c4 + t;
                    Ksf[((r >> 3) * 8 + (c >> 4)) * TILE_F
                        + (((r & 7) << 2) | (c & 3)) * 4 + ((c >> 2) & 3)] = va[t];
                }
            }
            {   // V row r = k; col c = head dim
                float va[4] = {vv.x, vv.y, vv.z, vv.w};
#pragma unroll
                for (int t = 0; t < 4; t++) {
                    int c = c4 + t;
                    Vsf[((c >> 3) * 4 + (r >> 4)) * TILE_F
                        + (((c & 7) << 2) | (r & 3)) * 4 + ((r >> 2) & 3)] = va[t];
                }
            }
        }
        __syncthreads();

        // ---- S = Q K^T : warp computes 16 x 32 (its ch half) ----
        float s[4][4];
#pragma unroll
        for (int nt = 0; nt < 4; nt++)
#pragma unroll
            for (int i = 0; i < 4; i++) s[nt][i] = 0.f;

#pragma unroll
        for (int ksp = 0; ksp < 8; ksp++) {
            float4 A0 = *(float4*)&Qsf[(rg * 16 + 2 * ksp    ) * TILE_F + lane * 4];
            float4 A1 = *(float4*)&Qsf[(rg * 16 + 2 * ksp + 1) * TILE_F + lane * 4];
#pragma unroll
            for (int nt = 0; nt < 4; nt++) {
                float4 Bv = *(float4*)&Ksf[((ch * 4 + nt) * 8 + ksp) * TILE_F + lane * 4];
                mma_tf32(s[nt], U(A0.x), U(A0.y), U(A0.z), U(A0.w), U(Bv.x), U(Bv.y));
                mma_tf32(s[nt], U(A1.x), U(A1.y), U(A1.z), U(A1.w), U(Bv.z), U(Bv.w));
            }
        }

        // ---- causal mask on diagonal tile ----
        if (kt == qt) {
#pragma unroll
            for (int nt = 0; nt < 4; nt++) {
                int c0 = ch * 32 + nt * 8 + 2 * t4;
                if (c0     > r1) s[nt][0] = -1e30f;
                if (c0 + 1 > r1) s[nt][1] = -1e30f;
                if (c0     > r2) s[nt][2] = -1e30f;
                if (c0 + 1 > r2) s[nt][3] = -1e30f;
            }
        }

        // ---- partial row max over own 32 cols (shfl within t4 group) ----
        float mx1 = -1e30f, mx2 = -1e30f;
#pragma unroll
        for (int nt = 0; nt < 4; nt++) {
            mx1 = fmaxf(mx1, fmaxf(s[nt][0], s[nt][1]));
            mx2 = fmaxf(mx2, fmaxf(s[nt][2], s[nt][3]));
        }
        mx1 = fmaxf(mx1, __shfl_xor_sync(0xffffffffu, mx1, 1));
        mx1 = fmaxf(mx1, __shfl_xor_sync(0xffffffffu, mx1, 2));
        mx2 = fmaxf(mx2, __shfl_xor_sync(0xffffffffu, mx2, 1));
        mx2 = fmaxf(mx2, __shfl_xor_sync(0xffffffffu, mx2, 2));
        if (t4 == 0) {
            smax[ch * 64 + r1] = mx1;
            smax[ch * 64 + r2] = mx2;
        }
        __syncthreads();   // stats_max ready; all S-reads of Ksf done -> K dead

        // ---- global max, exp, partial sums; write P A-frags into Ksf ----
        float omx1 = smax[(1 - ch) * 64 + r1];
        float omx2 = smax[(1 - ch) * 64 + r2];
        float mn1 = fmaxf(m1, fmaxf(mx1, omx1));
        float mn2 = fmaxf(m2, fmaxf(mx2, omx2));
        float al1 = __expf(m1 - mn1), al2 = __expf(m2 - mn2);
        m1 = mn1; m2 = mn2;

        float sum1 = 0.f, sum2 = 0.f;
        {
            int lane0 = g * 4 + ((2 * t4) & 3);
            int lane1 = g * 4 + ((2 * t4 + 1) & 3);
            int rebase = ((2 * t4) >> 2) << 1;     // 0 or 2
#pragma unroll
            for (int nt = 0; nt < 4; nt++) {
                float p0 = __expf(s[nt][0] - mn1);
                float p1 = __expf(s[nt][1] - mn1);
                float p2 = __expf(s[nt][2] - mn2);
                float p3 = __expf(s[nt][3] - mn2);
                sum1 += p0 + p1; sum2 += p2 + p3;
                float* pt = &Ksf[(rg * 8 + ch * 4 + nt) * TILE_F];
                pt[lane0 * 4 + rebase    ] = f2tf(p0);
                pt[lane1 * 4 + rebase    ] = f2tf(p1);
                pt[lane0 * 4 + rebase + 1] = f2tf(p2);
                pt[lane1 * 4 + rebase + 1] = f2tf(p3);
            }
        }
        sum1 += __shfl_xor_sync(0xffffffffu, sum1, 1);
        sum1 += __shfl_xor_sync(0xffffffffu, sum1, 2);
        sum2 += __shfl_xor_sync(0xffffffffu, sum2, 1);
        sum2 += __shfl_xor_sync(0xffffffffu, sum2, 2);
        if (t4 == 0) {
            ssum[ch * 64 + r1] = sum1;
            ssum[ch * 64 + r2] = sum2;
        }
        __syncthreads();   // P + partial sums ready

        l1 = l1 * al1 + sum1 + ssum[(1 - ch) * 64 + r1];
        l2 = l2 * al2 + sum2 + ssum[(1 - ch) * 64 + r2];

        // ---- rescale O, then O += P V (P from Ksf overlay, V from Vsf) ----
#pragma unroll
        for (int nt = 0; nt < 8; nt++) {
            o[nt][0] *= al1; o[nt][1] *= al1;
            o[nt][2] *= al2; o[nt][3] *= al2;
        }
#pragma unroll
        for (int ksp = 0; ksp < 4; ksp++) {
            float4 P0 = *(float4*)&Ksf[(rg * 8 + 2 * ksp    ) * TILE_F + lane * 4];
            float4 P1 = *(float4*)&Ksf[(rg * 8 + 2 * ksp + 1) * TILE_F + lane * 4];
#pragma unroll
            for (int nt = 0; nt < 8; nt++) {
                float4 Bv = *(float4*)&Vsf[((ch * 8 + nt) * 4 + ksp) * TILE_F + lane * 4];
                mma_tf32(o[nt], U(P0.x), U(P0.y), U(P0.z), U(P0.w), U(Bv.x), U(Bv.y));
                mma_tf32(o[nt], U(P1.x), U(P1.y), U(P1.z), U(P1.w), U(Bv.z), U(Bv.w));
            }
        }
    }

    // ---- epilogue ----
    {
        float inv1 = 1.f / l1, inv2 = 1.f / l2;
        size_t base1 = ((size_t)b * TT + q0 + r1) * HH;
        size_t base2 = ((size_t)b * TT + q0 + r2) * HH;
#pragma unroll
        for (int nt = 0; nt < 8; nt++) {
            int col = ch * 64 + nt * 8 + 2 * t4;
            *(float2*)&out[base1 + col] = make_float2(o[nt][0] * inv1, o[nt][1] * inv1);
            *(float2*)&out[base2 + col] = make_float2(o[nt][2] * inv2, o[nt][3] * inv2);
        }
    }
}

// ---------------------------------------------------------------------------
extern "C" void kernel_launch(void* const* d_in, const int* in_sizes, int n_in,
                              void* d_out, int out_size)
{
    const float* x  = (const float*)d_in[0];
    const float* Wq = (const float*)d_in[1];
    const float* Wk = (const float*)d_in[2];
    const float* Wv = (const float*)d_in[3];
    float* out = (float*)d_out;

    qkv_kernel<<<dim3(MM / 128, 3), 256>>>(x, Wq, Wk, Wv);

    cudaFuncSetAttribute(attn_kernel,
                         cudaFuncAttributeMaxDynamicSharedMemorySize, ATTN_SMEM);
    attn_kernel<<<dim3(32, BB), 256, ATTN_SMEM>>>(out);
}

// round 13
// speedup vs baseline: 2.0370x; 2.0370x over previous
#include <cuda_runtime.h>

#define BB 8
#define TT 2048
#define EE 1024
#define HH 128
#define MM (BB*TT)
#define SCALE 0.08838834764831845f   // 1/sqrt(128)

// Scratch for projected Q/K/V (tf32-rounded; Q pre-scaled)
__device__ float g_Q[MM*HH];
__device__ float g_K[MM*HH];
__device__ float g_V[MM*HH];

__device__ __forceinline__ float f2tf(float f) {
    unsigned r;
    asm("cvt.rna.tf32.f32 %0, %1;" : "=r"(r) : "f"(f));
    return __uint_as_float(r);
}

__device__ __forceinline__ void mma_tf32(float* c,
    unsigned a0, unsigned a1, unsigned a2, unsigned a3,
    unsigned b0, unsigned b1)
{
    asm volatile(
        "mma.sync.aligned.m16n8k8.row.col.f32.tf32.tf32.f32 "
        "{%0,%1,%2,%3},{%4,%5,%6,%7},{%8,%9},{%0,%1,%2,%3};"
        : "+f"(c[0]), "+f"(c[1]), "+f"(c[2]), "+f"(c[3])
        : "r"(a0), "r"(a1), "r"(a2), "r"(a3), "r"(b0), "r"(b1));
}
#define U(x) __float_as_uint(x)

// qt permutation: co-resident pairs get complementary causal workloads.
__constant__ int QT_MAP[32] = {
    31,27,23,19, 2, 6,10,14,30,26,22,18, 3, 7,11,15,
    29,25,21,17, 0, 4, 8,12,28,24,20,16, 1, 5, 9,13};

// ---------------------------------------------------------------------------
// Kernel 1: QKV projection (tf32 mma). Outputs tf32-rounded; Q pre-scaled.
// (unchanged — measured-good)
// ---------------------------------------------------------------------------
__global__ __launch_bounds__(256) void qkv_kernel(
    const float* __restrict__ x,
    const float* __restrict__ Wq,
    const float* __restrict__ Wk,
    const float* __restrict__ Wv)
{
    __shared__ float As[128][36];
    __shared__ float Bs[32][136];

    const int mb = blockIdx.x;
    const int w3 = blockIdx.y;
    const float* Wp   = (w3 == 0) ? Wq : ((w3 == 1) ? Wk : Wv);
    float*       outp = (w3 == 0) ? g_Q : ((w3 == 1) ? g_K : g_V);
    const float  oscale = (w3 == 0) ? SCALE : 1.0f;

    const int tid  = threadIdx.x;
    const int lane = tid & 31;
    const int w    = tid >> 5;
    const int g    = lane >> 2;
    const int t4   = lane & 3;
    const int wm   = (w >> 1) * 32;
    const int wn   = (w & 1) * 64;
    const int m0   = mb * 128;

    float acc[2][8][4];
#pragma unroll
    for (int mt = 0; mt < 2; mt++)
#pragma unroll
        for (int nt = 0; nt < 8; nt++)
#pragma unroll
            for (int i = 0; i < 4; i++) acc[mt][nt][i] = 0.f;

    float4 xa[4], wa[4];
#pragma unroll
    for (int i = 0; i < 4; i++) {
        int lin = tid + i * 256;
        int r = lin >> 3, c = (lin & 7) * 4;
        xa[i] = *(const float4*)&x[(size_t)(m0 + r) * EE + c];
    }
#pragma unroll
    for (int i = 0; i < 4; i++) {
        int lin = tid + i * 256;
        int r = lin >> 5, c = (lin & 31) * 4;
        wa[i] = *(const float4*)&Wp[(size_t)r * HH + c];
    }

    for (int k0 = 0; k0 < EE; k0 += 32) {
#pragma unroll
        for (int i = 0; i < 4; i++) {
            int lin = tid + i * 256;
            int r = lin >> 3, c = (lin & 7) * 4;
            As[r][c + 0] = f2tf(xa[i].x);
            As[r][c + 1] = f2tf(xa[i].y);
            As[r][c + 2] = f2tf(xa[i].z);
            As[r][c + 3] = f2tf(xa[i].w);
        }
#pragma unroll
        for (int i = 0; i < 4; i++) {
            int lin = tid + i * 256;
            int r = lin >> 5, c = (lin & 31) * 4;
            Bs[r][c + 0] = f2tf(wa[i].x);
            Bs[r][c + 1] = f2tf(wa[i].y);
            Bs[r][c + 2] = f2tf(wa[i].z);
            Bs[r][c + 3] = f2tf(wa[i].w);
        }
        __syncthreads();

        if (k0 + 32 < EE) {
            int kn = k0 + 32;
#pragma unroll
            for (int i = 0; i < 4; i++) {
                int lin = tid + i * 256;
                int r = lin >> 3, c = (lin & 7) * 4;
                xa[i] = *(const float4*)&x[(size_t)(m0 + r) * EE + kn + c];
            }
#pragma unroll
            for (int i = 0; i < 4; i++) {
                int lin = tid + i * 256;
                int r = lin >> 5, c = (lin & 31) * 4;
                wa[i] = *(const float4*)&Wp[(size_t)(kn + r) * HH + c];
            }
        }

#pragma unroll
        for (int ks = 0; ks < 4; ks++) {
            unsigned a[2][4];
#pragma unroll
            for (int mt = 0; mt < 2; mt++) {
                a[mt][0] = U(As[wm + mt * 16 + g    ][ks * 8 + t4    ]);
                a[mt][1] = U(As[wm + mt * 16 + g + 8][ks * 8 + t4    ]);
                a[mt][2] = U(As[wm + mt * 16 + g    ][ks * 8 + t4 + 4]);
                a[mt][3] = U(As[wm + mt * 16 + g + 8][ks * 8 + t4 + 4]);
            }
#pragma unroll
            for (int nt = 0; nt < 8; nt++) {
                unsigned b0 = U(Bs[ks * 8 + t4    ][wn + nt * 8 + g]);
                unsigned b1 = U(Bs[ks * 8 + t4 + 4][wn + nt * 8 + g]);
                mma_tf32(acc[0][nt], a[0][0], a[0][1], a[0][2], a[0][3], b0, b1);
                mma_tf32(acc[1][nt], a[1][0], a[1][1], a[1][2], a[1][3], b0, b1);
            }
        }
        __syncthreads();
    }

#pragma unroll
    for (int mt = 0; mt < 2; mt++) {
#pragma unroll
        for (int nt = 0; nt < 8; nt++) {
            int row = m0 + wm + mt * 16 + g;
            int col = wn + nt * 8 + 2 * t4;
            float2 v0 = make_float2(f2tf(acc[mt][nt][0] * oscale), f2tf(acc[mt][nt][1] * oscale));
            float2 v1 = make_float2(f2tf(acc[mt][nt][2] * oscale), f2tf(acc[mt][nt][3] * oscale));
            *(float2*)&outp[(size_t)row * HH + col]       = v0;
            *(float2*)&outp[(size_t)(row + 8) * HH + col] = v1;
        }
    }
}

// ---------------------------------------------------------------------------
// Kernel 2: causal flash attention — R3 structure (row-major padded smem,
// scalar frag loads) + S-in-registers softmax + P overlaid into dead K buffer
// -> 101 KB smem -> 2 CTAs/SM.  256 threads = 8 warps.
// Warp w: rg=w>>1 (16 q-rows), ch=w&1 (32-col half of S; 64-col half of O).
// ---------------------------------------------------------------------------
#define QSS 132
#define VSS 136
#define ATTN_SMEM ((64*QSS + 64*QSS + 64*VSS + 256) * 4)   // 103424 B

__global__ __launch_bounds__(256, 2) void attn_kernel(float* __restrict__ out)
{
    extern __shared__ float sh[];
    float* Qs   = sh;                  // [64][132] tf32, pre-scaled
    float* Ks   = Qs + 64 * QSS;       // [64][132] tf32; P overlays after stats barrier
    float* Vs   = Ks + 64 * QSS;       // [64][136] tf32
    float* smax = Vs + 64 * VSS;       // [2][64] partial row max
    float* ssum = smax + 128;          // [2][64] partial row sum

    const int b  = blockIdx.y;
    const int qt = QT_MAP[blockIdx.x];
    const int q0 = qt * 64;

    const int tid  = threadIdx.x;
    const int lane = tid & 31;
    const int w    = tid >> 5;
    const int g    = lane >> 2;
    const int t4   = lane & 3;
    const int rg   = w >> 1;
    const int ch   = w & 1;
    const int r1   = rg * 16 + g;
    const int r2   = r1 + 8;

    // ---- load Q tile (already tf32+scaled) ----
    const float* Qg = g_Q + ((size_t)b * TT + q0) * HH;
#pragma unroll
    for (int i = 0; i < 8; i++) {
        int lin = tid + i * 256;               // 2048 float4
        int r = lin >> 5, c = (lin & 31) * 4;
        float4 v = *(const float4*)&Qg[(size_t)r * HH + c];
        Qs[r * QSS + c + 0] = v.x;
        Qs[r * QSS + c + 1] = v.y;
        Qs[r * QSS + c + 2] = v.z;
        Qs[r * QSS + c + 3] = v.w;
    }

    float m1 = -1e30f, m2 = -1e30f, l1 = 0.f, l2 = 0.f;
    float o[8][4];
#pragma unroll
    for (int nt = 0; nt < 8; nt++)
#pragma unroll
        for (int i = 0; i < 4; i++) o[nt][i] = 0.f;

    for (int kt = 0; kt <= qt; kt++) {
        if (kt) __syncthreads();   // prev iter's P/V reads done before overwrite
        const int k0 = kt * 64;
        const float* Kg = g_K + ((size_t)b * TT + k0) * HH;
        const float* Vg = g_V + ((size_t)b * TT + k0) * HH;

        // ---- load K,V tiles (row-major, conflict-free float4 path) ----
#pragma unroll
        for (int i = 0; i < 8; i++) {
            int lin = tid + i * 256;
            int r = lin >> 5, c = (lin & 31) * 4;
            float4 kv = *(const float4*)&Kg[(size_t)r * HH + c];
            float4 vv = *(const float4*)&Vg[(size_t)r * HH + c];
            Ks[r * QSS + c + 0] = kv.x;
            Ks[r * QSS + c + 1] = kv.y;
            Ks[r * QSS + c + 2] = kv.z;
            Ks[r * QSS + c + 3] = kv.w;
            Vs[r * VSS + c + 0] = vv.x;
            Vs[r * VSS + c + 1] = vv.y;
            Vs[r * VSS + c + 2] = vv.z;
            Vs[r * VSS + c + 3] = vv.w;
        }
        __syncthreads();

        // ---- S = Q K^T : warp computes 16 x 32 (its ch half), 16 k-steps ----
        float s[4][4];
#pragma unroll
        for (int nt = 0; nt < 4; nt++)
#pragma unroll
            for (int i = 0; i < 4; i++) s[nt][i] = 0.f;

#pragma unroll
        for (int ks = 0; ks < 16; ks++) {
            unsigned a0 = U(Qs[r1 * QSS + ks * 8 + t4    ]);
            unsigned a1 = U(Qs[r2 * QSS + ks * 8 + t4    ]);
            unsigned a2 = U(Qs[r1 * QSS + ks * 8 + t4 + 4]);
            unsigned a3 = U(Qs[r2 * QSS + ks * 8 + t4 + 4]);
#pragma unroll
            for (int nt = 0; nt < 4; nt++) {
                int kr = ch * 32 + nt * 8 + g;
                unsigned b0 = U(Ks[kr * QSS + ks * 8 + t4    ]);
                unsigned b1 = U(Ks[kr * QSS + ks * 8 + t4 + 4]);
                mma_tf32(s[nt], a0, a1, a2, a3, b0, b1);
            }
        }

        // ---- causal mask on diagonal tile ----
        if (kt == qt) {
#pragma unroll
            for (int nt = 0; nt < 4; nt++) {
                int c0 = ch * 32 + nt * 8 + 2 * t4;
                if (c0     > r1) s[nt][0] = -1e30f;
                if (c0 + 1 > r1) s[nt][1] = -1e30f;
                if (c0     > r2) s[nt][2] = -1e30f;
                if (c0 + 1 > r2) s[nt][3] = -1e30f;
            }
        }

        // ---- partial row max over own 32 cols ----
        float mx1 = -1e30f, mx2 = -1e30f;
#pragma unroll
        for (int nt = 0; nt < 4; nt++) {
            mx1 = fmaxf(mx1, fmaxf(s[nt][0], s[nt][1]));
            mx2 = fmaxf(mx2, fmaxf(s[nt][2], s[nt][3]));
        }
        mx1 = fmaxf(mx1, __shfl_xor_sync(0xffffffffu, mx1, 1));
        mx1 = fmaxf(mx1, __shfl_xor_sync(0xffffffffu, mx1, 2));
        mx2 = fmaxf(mx2, __shfl_xor_sync(0xffffffffu, mx2, 1));
        mx2 = fmaxf(mx2, __shfl_xor_sync(0xffffffffu, mx2, 2));
        if (t4 == 0) {
            smax[ch * 64 + r1] = mx1;
            smax[ch * 64 + r2] = mx2;
        }
        __syncthreads();   // max stats ready; ALL warps done reading Ks -> K dead

        // ---- global max, exp, write P row-major into Ks overlay ----
        float mn1 = fmaxf(m1, fmaxf(mx1, smax[(1 - ch) * 64 + r1]));
        float mn2 = fmaxf(m2, fmaxf(mx2, smax[(1 - ch) * 64 + r2]));
        float al1 = __expf(m1 - mn1), al2 = __expf(m2 - mn2);
        m1 = mn1; m2 = mn2;

        float sum1 = 0.f, sum2 = 0.f;
#pragma unroll
        for (int nt = 0; nt < 4; nt++) {
            int c0 = ch * 32 + nt * 8 + 2 * t4;
            float p0 = __expf(s[nt][0] - mn1);
            float p1 = __expf(s[nt][1] - mn1);
            float p2 = __expf(s[nt][2] - mn2);
            float p3 = __expf(s[nt][3] - mn2);
            sum1 += p0 + p1; sum2 += p2 + p3;
            *(float2*)&Ks[r1 * QSS + c0] = make_float2(f2tf(p0), f2tf(p1));
            *(float2*)&Ks[r2 * QSS + c0] = make_float2(f2tf(p2), f2tf(p3));
        }
        sum1 += __shfl_xor_sync(0xffffffffu, sum1, 1);
        sum1 += __shfl_xor_sync(0xffffffffu, sum1, 2);
        sum2 += __shfl_xor_sync(0xffffffffu, sum2, 1);
        sum2 += __shfl_xor_sync(0xffffffffu, sum2, 2);
        if (t4 == 0) {
            ssum[ch * 64 + r1] = sum1;
            ssum[ch * 64 + r2] = sum2;
        }
        __syncthreads();   // P + partial sums visible

        l1 = l1 * al1 + sum1 + ssum[(1 - ch) * 64 + r1];
        l2 = l2 * al2 + sum2 + ssum[(1 - ch) * 64 + r2];

        // ---- rescale O, then O += P V (P from Ks overlay, R3 indexing) ----
#pragma unroll
        for (int nt = 0; nt < 8; nt++) {
            o[nt][0] *= al1; o[nt][1] *= al1;
            o[nt][2] *= al2; o[nt][3] *= al2;
        }
#pragma unroll
        for (int ks = 0; ks < 8; ks++) {
            unsigned a0 = U(Ks[r1 * QSS + ks * 8 + t4    ]);
            unsigned a1 = U(Ks[r2 * QSS + ks * 8 + t4    ]);
            unsigned a2 = U(Ks[r1 * QSS + ks * 8 + t4 + 4]);
            unsigned a3 = U(Ks[r2 * QSS + ks * 8 + t4 + 4]);
#pragma unroll
            for (int nt = 0; nt < 8; nt++) {
                int col = ch * 64 + nt * 8 + g;
                unsigned b0 = U(Vs[(ks * 8 + t4    ) * VSS + col]);
                unsigned b1 = U(Vs[(ks * 8 + t4 + 4) * VSS + col]);
                mma_tf32(o[nt], a0, a1, a2, a3, b0, b1);
            }
        }
    }

    // ---- epilogue ----
    {
        float inv1 = 1.f / l1, inv2 = 1.f / l2;
        size_t base1 = ((size_t)b * TT + q0 + r1) * HH;
        size_t base2 = ((size_t)b * TT + q0 + r2) * HH;
#pragma unroll
        for (int nt = 0; nt < 8; nt++) {
            int col = ch * 64 + nt * 8 + 2 * t4;
            *(float2*)&out[base1 + col] = make_float2(o[nt][0] * inv1, o[nt][1] * inv1);
            *(float2*)&out[base2 + col] = make_float2(o[nt][2] * inv2, o[nt][3] * inv2);
        }
    }
}

// ---------------------------------------------------------------------------
extern "C" void kernel_launch(void* const* d_in, const int* in_sizes, int n_in,
                              void* d_out, int out_size)
{
    const float* x  = (const float*)d_in[0];
    const float* Wq = (const float*)d_in[1];
    const float* Wk = (const float*)d_in[2];
    const float* Wv = (const float*)d_in[3];
    float* out = (float*)d_out;

    qkv_kernel<<<dim3(MM / 128, 3), 256>>>(x, Wq, Wk, Wv);

    cudaFuncSetAttribute(attn_kernel,
                         cudaFuncAttributeMaxDynamicSharedMemorySize, ATTN_SMEM);
    attn_kernel<<<dim3(32, BB), 256, ATTN_SMEM>>>(out);
}

// round 14
// speedup vs baseline: 2.0812x; 1.0217x over previous
#include <cuda_runtime.h>

#define BB 8
#define TT 2048
#define EE 1024
#define HH 128
#define MM (BB*TT)
#define SCALE 0.08838834764831845f   // 1/sqrt(128)

// Q/K/V in FRAGMENT-TILE layout: per 64-row block, 64 tiles x 128 floats.
__device__ float g_Q[MM*HH];
__device__ float g_K[MM*HH];
__device__ float g_V[MM*HH];

__device__ __forceinline__ float f2tf(float f) {
    unsigned r;
    asm("cvt.rna.tf32.f32 %0, %1;" : "=r"(r) : "f"(f));
    return __uint_as_float(r);
}

__device__ __forceinline__ void mma_tf32(float* c,
    unsigned a0, unsigned a1, unsigned a2, unsigned a3,
    unsigned b0, unsigned b1)
{
    asm volatile(
        "mma.sync.aligned.m16n8k8.row.col.f32.tf32.tf32.f32 "
        "{%0,%1,%2,%3},{%4,%5,%6,%7},{%8,%9},{%0,%1,%2,%3};"
        : "+f"(c[0]), "+f"(c[1]), "+f"(c[2]), "+f"(c[3])
        : "r"(a0), "r"(a1), "r"(a2), "r"(a3), "r"(b0), "r"(b1));
}
#define U(x) __float_as_uint(x)

// Scatter index into fragment-tile layout (per 64-row block of 8192 floats).
// w3=0: Q A-frag tiles [rg*16+kc];  w3=1: K B-frag tiles [(n>>3)*8+ksp];
// w3=2: V B-frag tiles [(h>>3)*4+ksp]
__device__ __forceinline__ size_t frag_idx(int w3, int m, int c) {
    int blk = m >> 6, R = m & 63;
    int tile, lane, reg;
    if (w3 == 0) {
        tile = (R >> 4) * 16 + (c >> 3);
        lane = ((R & 7) << 2) | (c & 3);
        reg  = ((R >> 3) & 1) | (((c >> 2) & 1) << 1);
    } else if (w3 == 1) {
        tile = (R >> 3) * 8 + (c >> 4);
        lane = ((R & 7) << 2) | (c & 3);
        reg  = (c >> 2) & 3;
    } else {
        tile = (c >> 3) * 4 + (R >> 4);
        lane = ((c & 7) << 2) | (R & 3);
        reg  = (R >> 2) & 3;
    }
    return (size_t)blk * 8192 + tile * 128 + lane * 4 + reg;
}

// qt permutation: co-resident pairs get complementary causal workloads.
__constant__ int QT_MAP[32] = {
    31,27,23,19, 2, 6,10,14,30,26,22,18, 3, 7,11,15,
    29,25,21,17, 0, 4, 8,12,28,24,20,16, 1, 5, 9,13};

// ---------------------------------------------------------------------------
// Kernel 1: QKV projection (tf32 mma) with fragment-layout scatter epilogue.
// ---------------------------------------------------------------------------
__global__ __launch_bounds__(256) void qkv_kernel(
    const float* __restrict__ x,
    const float* __restrict__ Wq,
    const float* __restrict__ Wk,
    const float* __restrict__ Wv)
{
    __shared__ float As[128][36];
    __shared__ float Bs[32][136];

    const int mb = blockIdx.x;
    const int w3 = blockIdx.y;
    const float* Wp   = (w3 == 0) ? Wq : ((w3 == 1) ? Wk : Wv);
    float*       outp = (w3 == 0) ? g_Q : ((w3 == 1) ? g_K : g_V);
    const float  oscale = (w3 == 0) ? SCALE : 1.0f;

    const int tid  = threadIdx.x;
    const int lane = tid & 31;
    const int w    = tid >> 5;
    const int g    = lane >> 2;
    const int t4   = lane & 3;
    const int wm   = (w >> 1) * 32;
    const int wn   = (w & 1) * 64;
    const int m0   = mb * 128;

    float acc[2][8][4];
#pragma unroll
    for (int mt = 0; mt < 2; mt++)
#pragma unroll
        for (int nt = 0; nt < 8; nt++)
#pragma unroll
            for (int i = 0; i < 4; i++) acc[mt][nt][i] = 0.f;

    float4 xa[4], wa[4];
#pragma unroll
    for (int i = 0; i < 4; i++) {
        int lin = tid + i * 256;
        int r = lin >> 3, c = (lin & 7) * 4;
        xa[i] = *(const float4*)&x[(size_t)(m0 + r) * EE + c];
    }
#pragma unroll
    for (int i = 0; i < 4; i++) {
        int lin = tid + i * 256;
        int r = lin >> 5, c = (lin & 31) * 4;
        wa[i] = *(const float4*)&Wp[(size_t)r * HH + c];
    }

    for (int k0 = 0; k0 < EE; k0 += 32) {
#pragma unroll
        for (int i = 0; i < 4; i++) {
            int lin = tid + i * 256;
            int r = lin >> 3, c = (lin & 7) * 4;
            As[r][c + 0] = f2tf(xa[i].x);
            As[r][c + 1] = f2tf(xa[i].y);
            As[r][c + 2] = f2tf(xa[i].z);
            As[r][c + 3] = f2tf(xa[i].w);
        }
#pragma unroll
        for (int i = 0; i < 4; i++) {
            int lin = tid + i * 256;
            int r = lin >> 5, c = (lin & 31) * 4;
            Bs[r][c + 0] = f2tf(wa[i].x);
            Bs[r][c + 1] = f2tf(wa[i].y);
            Bs[r][c + 2] = f2tf(wa[i].z);
            Bs[r][c + 3] = f2tf(wa[i].w);
        }
        __syncthreads();

        if (k0 + 32 < EE) {
            int kn = k0 + 32;
#pragma unroll
            for (int i = 0; i < 4; i++) {
                int lin = tid + i * 256;
                int r = lin >> 3, c = (lin & 7) * 4;
                xa[i] = *(const float4*)&x[(size_t)(m0 + r) * EE + kn + c];
            }
#pragma unroll
            for (int i = 0; i < 4; i++) {
                int lin = tid + i * 256;
                int r = lin >> 5, c = (lin & 31) * 4;
                wa[i] = *(const float4*)&Wp[(size_t)(kn + r) * HH + c];
            }
        }

#pragma unroll
        for (int ks = 0; ks < 4; ks++) {
            unsigned a[2][4];
#pragma unroll
            for (int mt = 0; mt < 2; mt++) {
                a[mt][0] = U(As[wm + mt * 16 + g    ][ks * 8 + t4    ]);
                a[mt][1] = U(As[wm + mt * 16 + g + 8][ks * 8 + t4    ]);
                a[mt][2] = U(As[wm + mt * 16 + g    ][ks * 8 + t4 + 4]);
                a[mt][3] = U(As[wm + mt * 16 + g + 8][ks * 8 + t4 + 4]);
            }
#pragma unroll
            for (int nt = 0; nt < 8; nt++) {
                unsigned b0 = U(Bs[ks * 8 + t4    ][wn + nt * 8 + g]);
                unsigned b1 = U(Bs[ks * 8 + t4 + 4][wn + nt * 8 + g]);
                mma_tf32(acc[0][nt], a[0][0], a[0][1], a[0][2], a[0][3], b0, b1);
                mma_tf32(acc[1][nt], a[1][0], a[1][1], a[1][2], a[1][3], b0, b1);
            }
        }
        __syncthreads();
    }

    // scatter epilogue into fragment-tile layout
#pragma unroll
    for (int mt = 0; mt < 2; mt++) {
#pragma unroll
        for (int nt = 0; nt < 8; nt++) {
            int row = m0 + wm + mt * 16 + g;
            int col = wn + nt * 8 + 2 * t4;
            outp[frag_idx(w3, row,     col    )] = f2tf(acc[mt][nt][0] * oscale);
            outp[frag_idx(w3, row,     col + 1)] = f2tf(acc[mt][nt][1] * oscale);
            outp[frag_idx(w3, row + 8, col    )] = f2tf(acc[mt][nt][2] * oscale);
            outp[frag_idx(w3, row + 8, col + 1)] = f2tf(acc[mt][nt][3] * oscale);
        }
    }
}

// ---------------------------------------------------------------------------
// Kernel 2: causal flash attention. 256 threads = 8 warps, 2 CTAs/SM.
// All operand tiles arrive pre-permuted; smem loads are dense float4 copies;
// all MMA operand fetches are single conflict-free LDS.128.
// P (row-major, stride 68) overlays the dead K region after the stats barrier.
// ---------------------------------------------------------------------------
#define PSS 68
#define ATTN_SMEM ((3*8192 + 256) * 4)   // 99328 B -> 2 CTAs/SM

__global__ __launch_bounds__(256, 2) void attn_kernel(float* __restrict__ out)
{
    extern __shared__ float sh[];
    float* Qf   = sh;                  // 64 A-frag tiles
    float* Kf   = Qf + 8192;           // 64 B-frag tiles; P overlays (64 x 68)
    float* Vf   = Kf + 8192;           // 64 B-frag tiles
    float* smax = Vf + 8192;           // [2][64]
    float* ssum = smax + 128;          // [2][64]

    const int b  = blockIdx.y;
    const int qt = QT_MAP[blockIdx.x];
    const int q0 = qt * 64;

    const int tid  = threadIdx.x;
    const int lane = tid & 31;
    const int w    = tid >> 5;
    const int g    = lane >> 2;
    const int t4   = lane & 3;
    const int rg   = w >> 1;
    const int ch   = w & 1;
    const int r1   = rg * 16 + g;
    const int r2   = r1 + 8;

    // ---- dense copy of Q fragment block ----
    const float4* Qg4 = (const float4*)(g_Q + (size_t)(b * 32 + qt) * 8192);
#pragma unroll
    for (int i = 0; i < 8; i++) {
        int lin = tid + i * 256;
        *(float4*)&Qf[lin * 4] = Qg4[lin];
    }

    float m1 = -1e30f, m2 = -1e30f, l1 = 0.f, l2 = 0.f;
    float o[8][4];
#pragma unroll
    for (int nt = 0; nt < 8; nt++)
#pragma unroll
        for (int i = 0; i < 4; i++) o[nt][i] = 0.f;

    for (int kt = 0; kt <= qt; kt++) {
        if (kt) __syncthreads();   // prev iter's P/V reads done before overwrite
        const float4* Kg4 = (const float4*)(g_K + (size_t)(b * 32 + kt) * 8192);
        const float4* Vg4 = (const float4*)(g_V + (size_t)(b * 32 + kt) * 8192);

        // ---- dense copy of K,V fragment blocks ----
#pragma unroll
        for (int i = 0; i < 8; i++) {
            int lin = tid + i * 256;
            *(float4*)&Kf[lin * 4] = Kg4[lin];
            *(float4*)&Vf[lin * 4] = Vg4[lin];
        }
        __syncthreads();

        // ---- S = Q K^T : warp computes 16 x 32 (its ch half) ----
        float s[4][4];
#pragma unroll
        for (int nt = 0; nt < 4; nt++)
#pragma unroll
            for (int i = 0; i < 4; i++) s[nt][i] = 0.f;

#pragma unroll
        for (int ksp = 0; ksp < 8; ksp++) {
            float4 A0 = *(float4*)&Qf[(rg * 16 + 2 * ksp    ) * 128 + lane * 4];
            float4 A1 = *(float4*)&Qf[(rg * 16 + 2 * ksp + 1) * 128 + lane * 4];
#pragma unroll
            for (int nt = 0; nt < 4; nt++) {
                float4 Bv = *(float4*)&Kf[((ch * 4 + nt) * 8 + ksp) * 128 + lane * 4];
                mma_tf32(s[nt], U(A0.x), U(A0.y), U(A0.z), U(A0.w), U(Bv.x), U(Bv.y));
                mma_tf32(s[nt], U(A1.x), U(A1.y), U(A1.z), U(A1.w), U(Bv.z), U(Bv.w));
            }
        }

        // ---- causal mask on diagonal tile ----
        if (kt == qt) {
#pragma unroll
            for (int nt = 0; nt < 4; nt++) {
                int c0 = ch * 32 + nt * 8 + 2 * t4;
                if (c0     > r1) s[nt][0] = -1e30f;
                if (c0 + 1 > r1) s[nt][1] = -1e30f;
                if (c0     > r2) s[nt][2] = -1e30f;
                if (c0 + 1 > r2) s[nt][3] = -1e30f;
            }
        }

        // ---- partial row max over own 32 cols ----
        float mx1 = -1e30f, mx2 = -1e30f;
#pragma unroll
        for (int nt = 0; nt < 4; nt++) {
            mx1 = fmaxf(mx1, fmaxf(s[nt][0], s[nt][1]));
            mx2 = fmaxf(mx2, fmaxf(s[nt][2], s[nt][3]));
        }
        mx1 = fmaxf(mx1, __shfl_xor_sync(0xffffffffu, mx1, 1));
        mx1 = fmaxf(mx1, __shfl_xor_sync(0xffffffffu, mx1, 2));
        mx2 = fmaxf(mx2, __shfl_xor_sync(0xffffffffu, mx2, 1));
        mx2 = fmaxf(mx2, __shfl_xor_sync(0xffffffffu, mx2, 2));
        if (t4 == 0) {
            smax[ch * 64 + r1] = mx1;
            smax[ch * 64 + r2] = mx2;
        }
        __syncthreads();   // stats ready; all S-reads of Kf done -> K dead

        // ---- global max, exp, write P row-major into Kf overlay ----
        float mn1 = fmaxf(m1, fmaxf(mx1, smax[(1 - ch) * 64 + r1]));
        float mn2 = fmaxf(m2, fmaxf(mx2, smax[(1 - ch) * 64 + r2]));
        float al1 = __expf(m1 - mn1), al2 = __expf(m2 - mn2);
        m1 = mn1; m2 = mn2;

        float sum1 = 0.f, sum2 = 0.f;
#pragma unroll
        for (int nt = 0; nt < 4; nt++) {
            int c0 = ch * 32 + nt * 8 + 2 * t4;
            float p0 = __expf(s[nt][0] - mn1);
            float p1 = __expf(s[nt][1] - mn1);
            float p2 = __expf(s[nt][2] - mn2);
            float p3 = __expf(s[nt][3] - mn2);
            sum1 += p0 + p1; sum2 += p2 + p3;
            *(float2*)&Kf[r1 * PSS + c0] = make_float2(f2tf(p0), f2tf(p1));
            *(float2*)&Kf[r2 * PSS + c0] = make_float2(f2tf(p2), f2tf(p3));
        }
        sum1 += __shfl_xor_sync(0xffffffffu, sum1, 1);
        sum1 += __shfl_xor_sync(0xffffffffu, sum1, 2);
        sum2 += __shfl_xor_sync(0xffffffffu, sum2, 1);
        sum2 += __shfl_xor_sync(0xffffffffu, sum2, 2);
        if (t4 == 0) {
            ssum[ch * 64 + r1] = sum1;
            ssum[ch * 64 + r2] = sum2;
        }
        __syncthreads();   // P + partial sums visible

        l1 = l1 * al1 + sum1 + ssum[(1 - ch) * 64 + r1];
        l2 = l2 * al2 + sum2 + ssum[(1 - ch) * 64 + r2];

        // ---- rescale O, then O += P V ----
#pragma unroll
        for (int nt = 0; nt < 8; nt++) {
            o[nt][0] *= al1; o[nt][1] *= al1;
            o[nt][2] *= al2; o[nt][3] *= al2;
        }
#pragma unroll
        for (int ksp = 0; ksp < 4; ksp++) {
            // A-frags of P for ks = 2*ksp (a*) and 2*ksp+1 (c*)
            unsigned a0 = U(Kf[r1 * PSS + ksp * 16 + t4        ]);
            unsigned a1 = U(Kf[r2 * PSS + ksp * 16 + t4        ]);
            unsigned a2 = U(Kf[r1 * PSS + ksp * 16 + t4 + 4    ]);
            unsigned a3 = U(Kf[r2 * PSS + ksp * 16 + t4 + 4    ]);
            unsigned c0 = U(Kf[r1 * PSS + ksp * 16 + 8 + t4    ]);
            unsigned c1 = U(Kf[r2 * PSS + ksp * 16 + 8 + t4    ]);
            unsigned c2 = U(Kf[r1 * PSS + ksp * 16 + 8 + t4 + 4]);
            unsigned c3 = U(Kf[r2 * PSS + ksp * 16 + 8 + t4 + 4]);
#pragma unroll
            for (int nt = 0; nt < 8; nt++) {
                float4 Bv = *(float4*)&Vf[((ch * 8 + nt) * 4 + ksp) * 128 + lane * 4];
                mma_tf32(o[nt], a0, a1, a2, a3, U(Bv.x), U(Bv.y));
                mma_tf32(o[nt], c0, c1, c2, c3, U(Bv.z), U(Bv.w));
            }
        }
    }

    // ---- epilogue ----
    {
        float inv1 = 1.f / l1, inv2 = 1.f / l2;
        size_t base1 = ((size_t)b * TT + q0 + r1) * HH;
        size_t base2 = ((size_t)b * TT + q0 + r2) * HH;
#pragma unroll
        for (int nt = 0; nt < 8; nt++) {
            int col = ch * 64 + nt * 8 + 2 * t4;
            *(float2*)&out[base1 + col] = make_float2(o[nt][0] * inv1, o[nt][1] * inv1);
            *(float2*)&out[base2 + col] = make_float2(o[nt][2] * inv2, o[nt][3] * inv2);
        }
    }
}

// ---------------------------------------------------------------------------
extern "C" void kernel_launch(void* const* d_in, const int* in_sizes, int n_in,
                              void* d_out, int out_size)
{
    const float* x  = (const float*)d_in[0];
    const float* Wq = (const float*)d_in[1];
    const float* Wk = (const float*)d_in[2];
    const float* Wv = (const float*)d_in[3];
    float* out = (float*)d_out;

    qkv_kernel<<<dim3(MM / 128, 3), 256>>>(x, Wq, Wk, Wv);

    cudaFuncSetAttribute(attn_kernel,
                         cudaFuncAttributeMaxDynamicSharedMemorySize, ATTN_SMEM);
    attn_kernel<<<dim3(32, BB), 256, ATTN_SMEM>>>(out);
}

// round 15
// speedup vs baseline: 2.6299x; 1.2637x over previous
#include <cuda_runtime.h>

#define BB 8
#define TT 2048
#define EE 1024
#define HH 128
#define MM (BB*TT)
#define SCALE 0.08838834764831845f   // 1/sqrt(128)

// Q/K/V in FRAGMENT-TILE layout: per 64-row block, 64 tiles x 128 floats.
__device__ float g_Q[MM*HH];
__device__ float g_K[MM*HH];
__device__ float g_V[MM*HH];

__device__ __forceinline__ float f2tf(float f) {
    unsigned r;
    asm("cvt.rna.tf32.f32 %0, %1;" : "=r"(r) : "f"(f));
    return __uint_as_float(r);
}

__device__ __forceinline__ void mma_tf32(float* c,
    unsigned a0, unsigned a1, unsigned a2, unsigned a3,
    unsigned b0, unsigned b1)
{
    asm volatile(
        "mma.sync.aligned.m16n8k8.row.col.f32.tf32.tf32.f32 "
        "{%0,%1,%2,%3},{%4,%5,%6,%7},{%8,%9},{%0,%1,%2,%3};"
        : "+f"(c[0]), "+f"(c[1]), "+f"(c[2]), "+f"(c[3])
        : "r"(a0), "r"(a1), "r"(a2), "r"(a3), "r"(b0), "r"(b1));
}
#define U(x) __float_as_uint(x)

__device__ __forceinline__ void cp_async16(unsigned saddr, const void* gaddr) {
    asm volatile("cp.async.cg.shared.global [%0], [%1], 16;"
                 :: "r"(saddr), "l"(gaddr));
}
#define CP_COMMIT() asm volatile("cp.async.commit_group;")
#define CP_WAIT0()  asm volatile("cp.async.wait_group 0;")

// Scatter index into fragment-tile layout (per 64-row block of 8192 floats).
__device__ __forceinline__ size_t frag_idx(int w3, int m, int c) {
    int blk = m >> 6, R = m & 63;
    int tile, lane, reg;
    if (w3 == 0) {
        tile = (R >> 4) * 16 + (c >> 3);
        lane = ((R & 7) << 2) | (c & 3);
        reg  = ((R >> 3) & 1) | (((c >> 2) & 1) << 1);
    } else if (w3 == 1) {
        tile = (R >> 3) * 8 + (c >> 4);
        lane = ((R & 7) << 2) | (c & 3);
        reg  = (c >> 2) & 3;
    } else {
        tile = (c >> 3) * 4 + (R >> 4);
        lane = ((c & 7) << 2) | (R & 3);
        reg  = (R >> 2) & 3;
    }
    return (size_t)blk * 8192 + tile * 128 + lane * 4 + reg;
}

// ---------------------------------------------------------------------------
// Kernel 1: QKV projection (tf32 mma) with fragment-layout scatter epilogue.
// (unchanged from R14)
// ---------------------------------------------------------------------------
__global__ __launch_bounds__(256) void qkv_kernel(
    const float* __restrict__ x,
    const float* __restrict__ Wq,
    const float* __restrict__ Wk,
    const float* __restrict__ Wv)
{
    __shared__ float As[128][36];
    __shared__ float Bs[32][136];

    const int mb = blockIdx.x;
    const int w3 = blockIdx.y;
    const float* Wp   = (w3 == 0) ? Wq : ((w3 == 1) ? Wk : Wv);
    float*       outp = (w3 == 0) ? g_Q : ((w3 == 1) ? g_K : g_V);
    const float  oscale = (w3 == 0) ? SCALE : 1.0f;

    const int tid  = threadIdx.x;
    const int lane = tid & 31;
    const int w    = tid >> 5;
    const int g    = lane >> 2;
    const int t4   = lane & 3;
    const int wm   = (w >> 1) * 32;
    const int wn   = (w & 1) * 64;
    const int m0   = mb * 128;

    float acc[2][8][4];
#pragma unroll
    for (int mt = 0; mt < 2; mt++)
#pragma unroll
        for (int nt = 0; nt < 8; nt++)
#pragma unroll
            for (int i = 0; i < 4; i++) acc[mt][nt][i] = 0.f;

    float4 xa[4], wa[4];
#pragma unroll
    for (int i = 0; i < 4; i++) {
        int lin = tid + i * 256;
        int r = lin >> 3, c = (lin & 7) * 4;
        xa[i] = *(const float4*)&x[(size_t)(m0 + r) * EE + c];
    }
#pragma unroll
    for (int i = 0; i < 4; i++) {
        int lin = tid + i * 256;
        int r = lin >> 5, c = (lin & 31) * 4;
        wa[i] = *(const float4*)&Wp[(size_t)r * HH + c];
    }

    for (int k0 = 0; k0 < EE; k0 += 32) {
#pragma unroll
        for (int i = 0; i < 4; i++) {
            int lin = tid + i * 256;
            int r = lin >> 3, c = (lin & 7) * 4;
            As[r][c + 0] = f2tf(xa[i].x);
            As[r][c + 1] = f2tf(xa[i].y);
            As[r][c + 2] = f2tf(xa[i].z);
            As[r][c + 3] = f2tf(xa[i].w);
        }
#pragma unroll
        for (int i = 0; i < 4; i++) {
            int lin = tid + i * 256;
            int r = lin >> 5, c = (lin & 31) * 4;
            Bs[r][c + 0] = f2tf(wa[i].x);
            Bs[r][c + 1] = f2tf(wa[i].y);
            Bs[r][c + 2] = f2tf(wa[i].z);
            Bs[r][c + 3] = f2tf(wa[i].w);
        }
        __syncthreads();

        if (k0 + 32 < EE) {
            int kn = k0 + 32;
#pragma unroll
            for (int i = 0; i < 4; i++) {
                int lin = tid + i * 256;
                int r = lin >> 3, c = (lin & 7) * 4;
                xa[i] = *(const float4*)&x[(size_t)(m0 + r) * EE + kn + c];
            }
#pragma unroll
            for (int i = 0; i < 4; i++) {
                int lin = tid + i * 256;
                int r = lin >> 5, c = (lin & 31) * 4;
                wa[i] = *(const float4*)&Wp[(size_t)(kn + r) * HH + c];
            }
        }

#pragma unroll
        for (int ks = 0; ks < 4; ks++) {
            unsigned a[2][4];
#pragma unroll
            for (int mt = 0; mt < 2; mt++) {
                a[mt][0] = U(As[wm + mt * 16 + g    ][ks * 8 + t4    ]);
                a[mt][1] = U(As[wm + mt * 16 + g + 8][ks * 8 + t4    ]);
                a[mt][2] = U(As[wm + mt * 16 + g    ][ks * 8 + t4 + 4]);
                a[mt][3] = U(As[wm + mt * 16 + g + 8][ks * 8 + t4 + 4]);
            }
#pragma unroll
            for (int nt = 0; nt < 8; nt++) {
                unsigned b0 = U(Bs[ks * 8 + t4    ][wn + nt * 8 + g]);
                unsigned b1 = U(Bs[ks * 8 + t4 + 4][wn + nt * 8 + g]);
                mma_tf32(acc[0][nt], a[0][0], a[0][1], a[0][2], a[0][3], b0, b1);
                mma_tf32(acc[1][nt], a[1][0], a[1][1], a[1][2], a[1][3], b0, b1);
            }
        }
        __syncthreads();
    }

#pragma unroll
    for (int mt = 0; mt < 2; mt++) {
#pragma unroll
        for (int nt = 0; nt < 8; nt++) {
            int row = m0 + wm + mt * 16 + g;
            int col = wn + nt * 8 + 2 * t4;
            outp[frag_idx(w3, row,     col    )] = f2tf(acc[mt][nt][0] * oscale);
            outp[frag_idx(w3, row,     col + 1)] = f2tf(acc[mt][nt][1] * oscale);
            outp[frag_idx(w3, row + 8, col    )] = f2tf(acc[mt][nt][2] * oscale);
            outp[frag_idx(w3, row + 8, col + 1)] = f2tf(acc[mt][nt][3] * oscale);
        }
    }
}

// ---------------------------------------------------------------------------
// Kernel 2: causal flash attention, 128-row q-tiles, warp-private softmax.
// 256 threads = 8 warps; warp w owns q-rows [16w,16w+16) x ALL 64 k-cols.
// cp.async double-buffered K/V; ONE __syncthreads per k-tile iteration.
// P converted C-frag -> A-frag via shfl (no smem round trip).
// smem: Q 64KB + K 2x32KB + V 2x32KB = 192KB -> 1 CTA/SM.
// ---------------------------------------------------------------------------
#define ATTN_SMEM ((16384 + 16384 + 16384) * 4)   // 196608 B

__global__ __launch_bounds__(256, 1) void attn_kernel(float* __restrict__ out)
{
    extern __shared__ float sh[];
    float* Qf = sh;             // 128 A-frag tiles (two 64-row blocks)
    float* Kf = Qf + 16384;     // 2 stages x 64 B-frag tiles
    float* Vf = Kf + 16384;     // 2 stages x 64 B-frag tiles

    const int b  = blockIdx.y;
    const int qt = blockIdx.x;          // 128-row q tile, 0..15
    const int q0 = qt * 128;
    const int nkt = 2 * qt + 2;         // 64-row k tiles

    const int tid  = threadIdx.x;
    const int lane = tid & 31;
    const int w    = tid >> 5;
    const int g    = lane >> 2;
    const int t4   = lane & 3;
    const int qoff = (w >> 2) * 8192 + (w & 3) * 16 * 128;  // warp's Q tiles
    const int row1 = q0 + 16 * w + g;   // global q rows of this lane
    const int row2 = row1 + 8;

    // ---- dense copy of the two Q fragment blocks ----
    const float4* Qg4 = (const float4*)(g_Q + ((size_t)b * 32 + 2 * qt) * 8192);
#pragma unroll
    for (int i = 0; i < 16; i++) {
        int lin = tid + i * 256;
        *(float4*)&Qf[lin * 4] = Qg4[lin];
    }

    // ---- prologue: cp.async K/V tile 0 into stage 0 ----
    {
        const char* Kg = (const char*)(g_K + (size_t)b * 32 * 8192);
        const char* Vg = (const char*)(g_V + (size_t)b * 32 * 8192);
        unsigned kbase = (unsigned)__cvta_generic_to_shared(Kf);
        unsigned vbase = (unsigned)__cvta_generic_to_shared(Vf);
#pragma unroll
        for (int i = 0; i < 8; i++) {
            int lin = tid + i * 256;
            cp_async16(kbase + lin * 16, Kg + lin * 16);
            cp_async16(vbase + lin * 16, Vg + lin * 16);
        }
        CP_COMMIT();
    }

    float m1 = -1e30f, m2 = -1e30f, l1 = 0.f, l2 = 0.f;
    float o[16][4];
#pragma unroll
    for (int nt = 0; nt < 16; nt++)
#pragma unroll
        for (int i = 0; i < 4; i++) o[nt][i] = 0.f;

    for (int kt = 0; kt < nkt; kt++) {
        CP_WAIT0();
        __syncthreads();   // stage kt data visible; prev compute done everywhere

        // issue next tile into the other stage (overlaps with compute below)
        if (kt + 1 < nkt) {
            int st = (kt + 1) & 1;
            const char* Kg = (const char*)(g_K + ((size_t)b * 32 + kt + 1) * 8192);
            const char* Vg = (const char*)(g_V + ((size_t)b * 32 + kt + 1) * 8192);
            unsigned kbase = (unsigned)__cvta_generic_to_shared(Kf + st * 8192);
            unsigned vbase = (unsigned)__cvta_generic_to_shared(Vf + st * 8192);
#pragma unroll
            for (int i = 0; i < 8; i++) {
                int lin = tid + i * 256;
                cp_async16(kbase + lin * 16, Kg + lin * 16);
                cp_async16(vbase + lin * 16, Vg + lin * 16);
            }
            CP_COMMIT();
        }

        // fully-masked half-tile: warps 0-3 idle on the last (odd) diagonal tile
        if (kt == 2 * qt + 1 && w < 4) continue;

        float* Ks = Kf + (kt & 1) * 8192;
        float* Vs = Vf + (kt & 1) * 8192;

        // ---- S = Q K^T : warp computes 16 x 64 ----
        float s[8][4];
#pragma unroll
        for (int nt = 0; nt < 8; nt++)
#pragma unroll
            for (int i = 0; i < 4; i++) s[nt][i] = 0.f;

#pragma unroll
        for (int ksp = 0; ksp < 8; ksp++) {
            float4 A0 = *(float4*)&Qf[qoff + (2 * ksp    ) * 128 + lane * 4];
            float4 A1 = *(float4*)&Qf[qoff + (2 * ksp + 1) * 128 + lane * 4];
#pragma unroll
            for (int nt = 0; nt < 8; nt++) {
                float4 Bv = *(float4*)&Ks[(nt * 8 + ksp) * 128 + lane * 4];
                mma_tf32(s[nt], U(A0.x), U(A0.y), U(A0.z), U(A0.w), U(Bv.x), U(Bv.y));
                mma_tf32(s[nt], U(A1.x), U(A1.y), U(A1.z), U(A1.w), U(Bv.z), U(Bv.w));
            }
        }

        // ---- causal mask (diagonal region: last two k tiles) ----
        if (kt >= 2 * qt) {
            int cb = kt * 64;
#pragma unroll
            for (int nt = 0; nt < 8; nt++) {
                int c0 = cb + nt * 8 + 2 * t4;
                if (c0     > row1) s[nt][0] = -1e30f;
                if (c0 + 1 > row1) s[nt][1] = -1e30f;
                if (c0     > row2) s[nt][2] = -1e30f;
                if (c0 + 1 > row2) s[nt][3] = -1e30f;
            }
        }

        // ---- warp-private online softmax ----
        float mx1 = -1e30f, mx2 = -1e30f;
#pragma unroll
        for (int nt = 0; nt < 8; nt++) {
            mx1 = fmaxf(mx1, fmaxf(s[nt][0], s[nt][1]));
            mx2 = fmaxf(mx2, fmaxf(s[nt][2], s[nt][3]));
        }
        mx1 = fmaxf(mx1, __shfl_xor_sync(0xffffffffu, mx1, 1));
        mx1 = fmaxf(mx1, __shfl_xor_sync(0xffffffffu, mx1, 2));
        mx2 = fmaxf(mx2, __shfl_xor_sync(0xffffffffu, mx2, 1));
        mx2 = fmaxf(mx2, __shfl_xor_sync(0xffffffffu, mx2, 2));

        float mn1 = fmaxf(m1, mx1), mn2 = fmaxf(m2, mx2);
        float al1 = __expf(m1 - mn1), al2 = __expf(m2 - mn2);
        m1 = mn1; m2 = mn2;

        float sum1 = 0.f, sum2 = 0.f;
#pragma unroll
        for (int nt = 0; nt < 8; nt++) {
            float p0 = __expf(s[nt][0] - mn1);
            float p1 = __expf(s[nt][1] - mn1);
            float p2 = __expf(s[nt][2] - mn2);
            float p3 = __expf(s[nt][3] - mn2);
            sum1 += p0 + p1; sum2 += p2 + p3;
            s[nt][0] = f2tf(p0); s[nt][1] = f2tf(p1);
            s[nt][2] = f2tf(p2); s[nt][3] = f2tf(p3);
        }
        sum1 += __shfl_xor_sync(0xffffffffu, sum1, 1);
        sum1 += __shfl_xor_sync(0xffffffffu, sum1, 2);
        sum2 += __shfl_xor_sync(0xffffffffu, sum2, 1);
        sum2 += __shfl_xor_sync(0xffffffffu, sum2, 2);
        l1 = l1 * al1 + sum1;
        l2 = l2 * al2 + sum2;

        // ---- rescale O ----
#pragma unroll
        for (int nt = 0; nt < 16; nt++) {
            o[nt][0] *= al1; o[nt][1] *= al1;
            o[nt][2] *= al2; o[nt][3] *= al2;
        }

        // ---- O += P V : P C-frags -> A-frags via shfl (validated in R5) ----
#pragma unroll
        for (int ksp = 0; ksp < 4; ksp++) {
            unsigned a[2][4];
#pragma unroll
            for (int h = 0; h < 2; h++) {
                int j = 2 * ksp + h;
                float p0 = s[j][0], p1 = s[j][1], p2 = s[j][2], p3 = s[j][3];
                int srcA = (lane & ~3) | (t4 >> 1);
                int srcB = srcA + 2;
                float u0 = __shfl_sync(0xffffffffu, p0, srcA);
                float v0 = __shfl_sync(0xffffffffu, p1, srcA);
                float u1 = __shfl_sync(0xffffffffu, p2, srcA);
                float v1 = __shfl_sync(0xffffffffu, p3, srcA);
                float u2 = __shfl_sync(0xffffffffu, p0, srcB);
                float v2 = __shfl_sync(0xffffffffu, p1, srcB);
                float u3 = __shfl_sync(0xffffffffu, p2, srcB);
                float v3 = __shfl_sync(0xffffffffu, p3, srcB);
                bool odd = (t4 & 1);
                a[h][0] = U(odd ? v0 : u0);
                a[h][1] = U(odd ? v1 : u1);
                a[h][2] = U(odd ? v2 : u2);
                a[h][3] = U(odd ? v3 : u3);
            }
#pragma unroll
            for (int nt = 0; nt < 16; nt++) {
                float4 Bv = *(float4*)&Vs[(nt * 4 + ksp) * 128 + lane * 4];
                mma_tf32(o[nt], a[0][0], a[0][1], a[0][2], a[0][3], U(Bv.x), U(Bv.y));
                mma_tf32(o[nt], a[1][0], a[1][1], a[1][2], a[1][3], U(Bv.z), U(Bv.w));
            }
        }
    }

    // ---- epilogue ----
    {
        float inv1 = 1.f / l1, inv2 = 1.f / l2;
        size_t base1 = ((size_t)b * TT + row1) * HH;
        size_t base2 = ((size_t)b * TT + row2) * HH;
#pragma unroll
        for (int nt = 0; nt < 16; nt++) {
            int col = nt * 8 + 2 * t4;
            *(float2*)&out[base1 + col] = make_float2(o[nt][0] * inv1, o[nt][1] * inv1);
            *(float2*)&out[base2 + col] = make_float2(o[nt][2] * inv2, o[nt][3] * inv2);
        }
    }
}

// ---------------------------------------------------------------------------
extern "C" void kernel_launch(void* const* d_in, const int* in_sizes, int n_in,
                              void* d_out, int out_size)
{
    const float* x  = (const float*)d_in[0];
    const float* Wq = (const float*)d_in[1];
    const float* Wk = (const float*)d_in[2];
    const float* Wv = (const float*)d_in[3];
    float* out = (float*)d_out;

    qkv_kernel<<<dim3(MM / 128, 3), 256>>>(x, Wq, Wk, Wv);

    cudaFuncSetAttribute(attn_kernel,
                         cudaFuncAttributeMaxDynamicSharedMemorySize, ATTN_SMEM);
    attn_kernel<<<dim3(16, BB), 256, ATTN_SMEM>>>(out);
}